// round 3
// baseline (speedup 1.0000x reference)
#include <cuda_runtime.h>
#include <cstdint>
#include <cstddef>

// ---------------------------------------------------------------------------
// Problem constants
// ---------------------------------------------------------------------------
#define VOCAB   16384
#define DDIM    1024
#define BATCH   8
#define TSTEPS  16
#define NLAYERS 4
#define LFSR_POLY 0x100Bu           // 69643 & 0xFFFF (bits 0,1,3,12)
#define SEEDS_PER_LAYER 65536       // VOCAB*DDIM/256
#define BLOCK_VALS 256
#define NSEEDS_TOT (NLAYERS * SEEDS_PER_LAYER)   // 262144

// toks [T,B] (as float) followed by logits [T,B,V] in d_out (float32)
#define TOKS_COUNT (TSTEPS*BATCH)

// ---------------------------------------------------------------------------
// Device scratch (static globals: allocation-free)
// ---------------------------------------------------------------------------
__device__ unsigned short g_wk[(size_t)NLAYERS * VOCAB * DDIM];  // 128 MB raw LFSR states
__device__ float g_xqT[DDIM * BATCH];   // quantized activations, transposed [d][b]
__device__ float g_tokf[TSTEPS * BATCH];

// ---------------------------------------------------------------------------
// threefry2x32-20 (exact JAX implementation)
// ---------------------------------------------------------------------------
__device__ __forceinline__ unsigned rotl32(unsigned x, int r) {
    return __funnelshift_l(x, x, r);
}

__device__ __forceinline__ uint2 threefry2x32(uint2 key, unsigned c0, unsigned c1) {
    unsigned ks0 = key.x, ks1 = key.y;
    unsigned ks2 = ks0 ^ ks1 ^ 0x1BD11BDAu;
    unsigned x0 = c0 + ks0;
    unsigned x1 = c1 + ks1;
#define TF_R4(a,b,c,d)                                              \
    x0 += x1; x1 = rotl32(x1,(a)); x1 ^= x0;                        \
    x0 += x1; x1 = rotl32(x1,(b)); x1 ^= x0;                        \
    x0 += x1; x1 = rotl32(x1,(c)); x1 ^= x0;                        \
    x0 += x1; x1 = rotl32(x1,(d)); x1 ^= x0;
    TF_R4(13,15,26,6);   x0 += ks1; x1 += ks2 + 1u;
    TF_R4(17,29,16,24);  x0 += ks2; x1 += ks0 + 2u;
    TF_R4(13,15,26,6);   x0 += ks0; x1 += ks1 + 3u;
    TF_R4(17,29,16,24);  x0 += ks1; x1 += ks2 + 4u;
    TF_R4(13,15,26,6);   x0 += ks2; x1 += ks0 + 5u;
#undef TF_R4
    return make_uint2(x0, x1);
}

// ---------------------------------------------------------------------------
// Kernel 1: LFSR decompression -> raw uint16 states, one thread per seed
// ---------------------------------------------------------------------------
__global__ void decompress_kernel(const int* __restrict__ seeds) {
    int sid = blockIdx.x * blockDim.x + threadIdx.x;   // 0 .. 262143
    unsigned state = ((unsigned)seeds[sid]) & 0xFFFFu;
    uint4* out = reinterpret_cast<uint4*>(g_wk + (size_t)sid * BLOCK_VALS);
#pragma unroll 4
    for (int m = 0; m < 32; m++) {
        unsigned short v[8];
#pragma unroll
        for (int e = 0; e < 8; e++) {
            v[e] = (unsigned short)state;
            unsigned fb = __popc(state & LFSR_POLY) & 1u;
            state = ((state >> 1) | (fb << 15)) & 0xFFFFu;
        }
        uint4 u;
        u.x = (unsigned)v[0] | ((unsigned)v[1] << 16);
        u.y = (unsigned)v[2] | ((unsigned)v[3] << 16);
        u.z = (unsigned)v[4] | ((unsigned)v[5] << 16);
        u.w = (unsigned)v[6] | ((unsigned)v[7] << 16);
        out[m] = u;
    }
}

// ---------------------------------------------------------------------------
// Kernel 2: prep — rolling buffer + layernorm + quantize (STE forward)
// One block, 1024 threads (one per d).
// ---------------------------------------------------------------------------
__global__ void prep_kernel(const float* __restrict__ x0, int t) {
    __shared__ float s_red[32][8];
    __shared__ float s_bcast[8];

    const int d    = threadIdx.x;
    const int lane = d & 31;
    const int wid  = d >> 5;

    float v[8];
#pragma unroll
    for (int b = 0; b < 8; b++) {
        if (d < DDIM - t) v[b] = x0[b * DDIM + d + t];
        else              v[b] = g_tokf[(size_t)(d + t - DDIM) * BATCH + b];
    }

    // ---- pass 1: mean ----
    float r[8];
#pragma unroll
    for (int b = 0; b < 8; b++) r[b] = v[b];
#pragma unroll
    for (int off = 16; off; off >>= 1)
#pragma unroll
        for (int b = 0; b < 8; b++) r[b] += __shfl_down_sync(0xFFFFFFFFu, r[b], off);
    if (lane == 0)
#pragma unroll
        for (int b = 0; b < 8; b++) s_red[wid][b] = r[b];
    __syncthreads();
    if (d < 32) {
        float w[8];
#pragma unroll
        for (int b = 0; b < 8; b++) w[b] = s_red[d][b];
#pragma unroll
        for (int off = 16; off; off >>= 1)
#pragma unroll
            for (int b = 0; b < 8; b++) w[b] += __shfl_down_sync(0xFFFFFFFFu, w[b], off);
        if (d == 0)
#pragma unroll
            for (int b = 0; b < 8; b++) s_bcast[b] = w[b] * (1.0f / DDIM);
    }
    __syncthreads();
    float mu[8];
#pragma unroll
    for (int b = 0; b < 8; b++) mu[b] = s_bcast[b];
    __syncthreads();

    // ---- pass 2: variance ----
#pragma unroll
    for (int b = 0; b < 8; b++) { float dv = v[b] - mu[b]; r[b] = dv * dv; }
#pragma unroll
    for (int off = 16; off; off >>= 1)
#pragma unroll
        for (int b = 0; b < 8; b++) r[b] += __shfl_down_sync(0xFFFFFFFFu, r[b], off);
    if (lane == 0)
#pragma unroll
        for (int b = 0; b < 8; b++) s_red[wid][b] = r[b];
    __syncthreads();
    if (d < 32) {
        float w[8];
#pragma unroll
        for (int b = 0; b < 8; b++) w[b] = s_red[d][b];
#pragma unroll
        for (int off = 16; off; off >>= 1)
#pragma unroll
            for (int b = 0; b < 8; b++) w[b] += __shfl_down_sync(0xFFFFFFFFu, w[b], off);
        if (d == 0)
#pragma unroll
            for (int b = 0; b < 8; b++) {
                float var = w[b] * (1.0f / DDIM);
                s_bcast[b] = 1.0f / sqrtf(var + 1e-5f);
            }
    }
    __syncthreads();
    float xn[8];
#pragma unroll
    for (int b = 0; b < 8; b++) xn[b] = (v[b] - mu[b]) * s_bcast[b];
    __syncthreads();

    // ---- pass 3: max |xn| ----
#pragma unroll
    for (int b = 0; b < 8; b++) r[b] = fabsf(xn[b]);
#pragma unroll
    for (int off = 16; off; off >>= 1)
#pragma unroll
        for (int b = 0; b < 8; b++) r[b] = fmaxf(r[b], __shfl_down_sync(0xFFFFFFFFu, r[b], off));
    if (lane == 0)
#pragma unroll
        for (int b = 0; b < 8; b++) s_red[wid][b] = r[b];
    __syncthreads();
    if (d < 32) {
        float w[8];
#pragma unroll
        for (int b = 0; b < 8; b++) w[b] = s_red[d][b];
#pragma unroll
        for (int off = 16; off; off >>= 1)
#pragma unroll
            for (int b = 0; b < 8; b++) w[b] = fmaxf(w[b], __shfl_down_sync(0xFFFFFFFFu, w[b], off));
        if (d == 0)
#pragma unroll
            for (int b = 0; b < 8; b++) s_bcast[b] = 127.0f / fmaxf(w[b], 1e-5f);
    }
    __syncthreads();

    // ---- quantize + store transposed ----
#pragma unroll
    for (int b = 0; b < 8; b++) {
        float as = s_bcast[b];
        float q  = rintf(fminf(fmaxf(xn[b] * as, -127.0f), 127.0f));
        g_xqT[(size_t)d * BATCH + b] = q / as;
    }
}

// ---------------------------------------------------------------------------
// Kernel 3: matmul  logits[t][b][v] = sum_d xq[b][d] * (k[v][d]-32768) * scale/32768
// 128 blocks x 256 threads. Warp = 16 rows: lane=(g,j), g=lane/8 picks 4-row
// group, j=lane%8 is D-slice. Each thread: 4 rows x 128 d-elements.
// ---------------------------------------------------------------------------
__global__ void __launch_bounds__(256) matmul_kernel(int t, const float* __restrict__ scales,
                                                     float* __restrict__ d_out) {
    __shared__ float s_xq[DDIM * BATCH];    // [d][b], 32 KB

    for (int i = threadIdx.x; i < DDIM * BATCH / 4; i += blockDim.x)
        reinterpret_cast<float4*>(s_xq)[i] = reinterpret_cast<const float4*>(g_xqT)[i];
    __syncthreads();

    const int l    = t & 3;
    const int warp = threadIdx.x >> 5;
    const int lane = threadIdx.x & 31;
    const int g    = lane >> 3;
    const int j    = lane & 7;
    const int v0   = blockIdx.x * 128 + warp * 16 + g * 4;

    const uint4* wrow = reinterpret_cast<const uint4*>(
        g_wk + ((size_t)l * VOCAB + v0) * DDIM);   // 128 uint4 per row

    float acc[4][8];
#pragma unroll
    for (int r = 0; r < 4; r++)
#pragma unroll
        for (int b = 0; b < 8; b++) acc[r][b] = 0.0f;

#pragma unroll 4
    for (int m = 0; m < 16; m++) {
        const int c = j + 8 * m;                 // uint4 index within row
        uint4 u0 = wrow[c];
        uint4 u1 = wrow[c + 128];
        uint4 u2 = wrow[c + 256];
        uint4 u3 = wrow[c + 384];
        unsigned w[4][4] = {
            {u0.x, u0.y, u0.z, u0.w},
            {u1.x, u1.y, u1.z, u1.w},
            {u2.x, u2.y, u2.z, u2.w},
            {u3.x, u3.y, u3.z, u3.w},
        };
        const int dbase = c * 8;
#pragma unroll
        for (int e = 0; e < 8; e++) {
            const float4 xa = *reinterpret_cast<const float4*>(&s_xq[(dbase + e) * BATCH]);
            const float4 xb = *reinterpret_cast<const float4*>(&s_xq[(dbase + e) * BATCH + 4]);
            const unsigned sel = (e & 1) ? 0x7432u : 0x7410u;
#pragma unroll
            for (int r = 0; r < 4; r++) {
                // f = 2^23 + k  (exact), then k - 32768 via one FADD
                float wf = __uint_as_float(__byte_perm(w[r][e >> 1], 0x4B000000u, sel))
                           - 8421376.0f;
                acc[r][0] += wf * xa.x;
                acc[r][1] += wf * xa.y;
                acc[r][2] += wf * xa.z;
                acc[r][3] += wf * xa.w;
                acc[r][4] += wf * xb.x;
                acc[r][5] += wf * xb.y;
                acc[r][6] += wf * xb.z;
                acc[r][7] += wf * xb.w;
            }
        }
    }

    // reduce over the 8 D-slice lanes (groups of 8 within the warp)
#pragma unroll
    for (int r = 0; r < 4; r++)
#pragma unroll
        for (int b = 0; b < 8; b++) {
            float a = acc[r][b];
            a += __shfl_down_sync(0xFFFFFFFFu, a, 4, 8);
            a += __shfl_down_sync(0xFFFFFFFFu, a, 2, 8);
            a += __shfl_down_sync(0xFFFFFFFFu, a, 1, 8);
            acc[r][b] = a;
        }

    if (j == 0) {
        const float cl = scales[l] * (1.0f / 32768.0f);
#pragma unroll
        for (int r = 0; r < 4; r++) {
            const int v = v0 + r;
#pragma unroll
            for (int b = 0; b < 8; b++) {
                d_out[TOKS_COUNT + ((size_t)t * BATCH + b) * VOCAB + v] = acc[r][b] * cl;
            }
        }
    }
}

// ---------------------------------------------------------------------------
// Kernel 4: sampler — Gumbel-max categorical.
// JAX threefry PARTITIONABLE ("foldlike") semantics (default since jax 0.5):
//   split(key,2):  key_i = full output (x,y) of threefry(key, c0=0, c1=i)
//   random_bits(key, 32, shape): flat idx i -> r = threefry(key, 0, i),
//                                bits = r.x ^ r.y
// 8 blocks (one per batch row) x 256 threads.
// ---------------------------------------------------------------------------
__global__ void sample_kernel(int t, float* __restrict__ d_out) {
    const int b   = blockIdx.x;
    const int tid = threadIdx.x;

    // key chain: key_0 = key(1) = (0,1); (key, sk) = split(key) each step
    uint2 key = make_uint2(0u, 1u);
    uint2 sk  = make_uint2(0u, 0u);
    for (int s = 0; s <= t; s++) {
        uint2 nk = threefry2x32(key, 0u, 0u);
        sk  = threefry2x32(key, 0u, 1u);
        key = nk;
    }

    const float* lg = d_out + TOKS_COUNT + ((size_t)t * BATCH + b) * VOCAB;

    float best = -__int_as_float(0x7f800000);   // -inf
    int   bi   = 0;
    const unsigned cbase = (unsigned)b * (unsigned)VOCAB;

    for (int k = 0; k < VOCAB / 256; k++) {
        const int v = tid + (k << 8);
        const unsigned ctr = cbase + (unsigned)v;   // flat index into (8,16384)
        uint2 r = threefry2x32(sk, 0u, ctr);        // (hi=0, lo=i)
        unsigned bits = r.x ^ r.y;
        float u01 = __uint_as_float((bits >> 9) | 0x3f800000u) - 1.0f;
        float u   = fmaxf(u01, 1.17549435e-38f);
        float gum = -logf(-logf(u));
        float val = lg[v] + gum;
        if (val > best || (val == best && v < bi)) { best = val; bi = v; }
    }

    __shared__ float sv[256];
    __shared__ int   si[256];
    sv[tid] = best; si[tid] = bi;
    __syncthreads();
    for (int off = 128; off > 0; off >>= 1) {
        if (tid < off) {
            float ov = sv[tid + off]; int oi = si[tid + off];
            if (ov > sv[tid] || (ov == sv[tid] && oi < si[tid])) { sv[tid] = ov; si[tid] = oi; }
        }
        __syncthreads();
    }
    if (tid == 0) {
        float tokf = (float)si[0];
        g_tokf[(size_t)t * BATCH + b] = tokf;
        d_out[(size_t)t * BATCH + b]  = tokf;   // toks occupy first T*B floats
    }
}

// ---------------------------------------------------------------------------
// Launch
// ---------------------------------------------------------------------------
extern "C" void kernel_launch(void* const* d_in, const int* in_sizes, int n_in,
                              void* d_out, int out_size) {
    const float* x0     = (const float*)d_in[0];   // [8,1024]
    const int*   seeds  = (const int*)d_in[1];     // [4,65536]
    const float* scales = (const float*)d_in[2];   // [4]
    float* out = (float*)d_out;

    decompress_kernel<<<NSEEDS_TOT / 256, 256>>>(seeds);

    for (int t = 0; t < TSTEPS; t++) {
        prep_kernel<<<1, 1024>>>(x0, t);
        matmul_kernel<<<VOCAB / 128, 256>>>(t, scales, out);
        sample_kernel<<<BATCH, 256>>>(t, out);
    }
}

// round 4
// speedup vs baseline: 1.4624x; 1.4624x over previous
#include <cuda_runtime.h>
#include <cstdint>
#include <cstddef>

// ---------------------------------------------------------------------------
// Problem constants
// ---------------------------------------------------------------------------
#define VOCAB   16384
#define DDIM    1024
#define BATCH   8
#define TSTEPS  16
#define NLAYERS 4
#define LFSR_POLY 0x100Bu           // 69643 & 0xFFFF (bits 0,1,3,12)
#define SEEDS_PER_LAYER 65536       // VOCAB*DDIM/256
#define BLOCK_VALS 256
#define NSEEDS_TOT (NLAYERS * SEEDS_PER_LAYER)   // 262144

// toks [T,B] (as float) followed by logits [T,B,V] in d_out (float32)
#define TOKS_COUNT (TSTEPS*BATCH)

// ---------------------------------------------------------------------------
// Device scratch (static globals: allocation-free)
// ---------------------------------------------------------------------------
__device__ unsigned short g_wk[(size_t)NLAYERS * VOCAB * DDIM];  // 128 MB raw LFSR states
__device__ float g_xqT[DDIM * BATCH];   // quantized activations, transposed [d][b]
__device__ float g_tokf[TSTEPS * BATCH];
__device__ unsigned long long g_best[BATCH];   // packed (ordered_val<<32)|(~v)

// ---------------------------------------------------------------------------
// threefry2x32-20 (exact JAX implementation), host+device
// ---------------------------------------------------------------------------
__host__ __device__ __forceinline__ unsigned rotl32(unsigned x, int r) {
#ifdef __CUDA_ARCH__
    return __funnelshift_l(x, x, r);
#else
    return (x << r) | (x >> (32 - r));
#endif
}

__host__ __device__ __forceinline__ uint2 threefry2x32(uint2 key, unsigned c0, unsigned c1) {
    unsigned ks0 = key.x, ks1 = key.y;
    unsigned ks2 = ks0 ^ ks1 ^ 0x1BD11BDAu;
    unsigned x0 = c0 + ks0;
    unsigned x1 = c1 + ks1;
#define TF_R4(a,b,c,d)                                              \
    x0 += x1; x1 = rotl32(x1,(a)); x1 ^= x0;                        \
    x0 += x1; x1 = rotl32(x1,(b)); x1 ^= x0;                        \
    x0 += x1; x1 = rotl32(x1,(c)); x1 ^= x0;                        \
    x0 += x1; x1 = rotl32(x1,(d)); x1 ^= x0;
    TF_R4(13,15,26,6);   x0 += ks1; x1 += ks2 + 1u;
    TF_R4(17,29,16,24);  x0 += ks2; x1 += ks0 + 2u;
    TF_R4(13,15,26,6);   x0 += ks0; x1 += ks1 + 3u;
    TF_R4(17,29,16,24);  x0 += ks1; x1 += ks2 + 4u;
    TF_R4(13,15,26,6);   x0 += ks2; x1 += ks0 + 5u;
#undef TF_R4
    uint2 out; out.x = x0; out.y = x1; return out;
}

// ordered-uint encoding of float for monotone unsigned compare
__device__ __forceinline__ unsigned orderf(float f) {
    unsigned u = __float_as_uint(f);
    return (u & 0x80000000u) ? ~u : (u | 0x80000000u);
}

// ---------------------------------------------------------------------------
// Kernel 1: LFSR decompression -> raw uint16 states, one thread per seed
// ---------------------------------------------------------------------------
__global__ void decompress_kernel(const int* __restrict__ seeds) {
    int sid = blockIdx.x * blockDim.x + threadIdx.x;   // 0 .. 262143
    unsigned state = ((unsigned)seeds[sid]) & 0xFFFFu;
    uint4* out = reinterpret_cast<uint4*>(g_wk + (size_t)sid * BLOCK_VALS);
#pragma unroll 4
    for (int m = 0; m < 32; m++) {
        unsigned short v[8];
#pragma unroll
        for (int e = 0; e < 8; e++) {
            v[e] = (unsigned short)state;
            unsigned fb = __popc(state & LFSR_POLY) & 1u;
            state = ((state >> 1) | (fb << 15)) & 0xFFFFu;
        }
        uint4 u;
        u.x = (unsigned)v[0] | ((unsigned)v[1] << 16);
        u.y = (unsigned)v[2] | ((unsigned)v[3] << 16);
        u.z = (unsigned)v[4] | ((unsigned)v[5] << 16);
        u.w = (unsigned)v[6] | ((unsigned)v[7] << 16);
        out[m] = u;
    }
}

// ---------------------------------------------------------------------------
// Kernel 2: prep — decode previous token, rolling buffer + layernorm + quantize
// One block, 1024 threads (one per d).
// ---------------------------------------------------------------------------
__global__ void prep_kernel(const float* __restrict__ x0, int t, float* __restrict__ d_out) {
    __shared__ float s_red[32][8];
    __shared__ float s_bcast[8];

    const int d    = threadIdx.x;
    const int lane = d & 31;
    const int wid  = d >> 5;

    // ---- decode step t-1 argmax from g_best, reset g_best for step t ----
    if (d < BATCH) {
        if (t > 0) {
            unsigned long long k = g_best[d];
            unsigned idx = 0xFFFFFFFFu - (unsigned)(k & 0xFFFFFFFFu);
            float tokf = (float)idx;
            g_tokf[(size_t)(t - 1) * BATCH + d] = tokf;
            d_out[(size_t)(t - 1) * BATCH + d]  = tokf;
        }
        g_best[d] = 0ull;
    }
    __syncthreads();

    float v[8];
#pragma unroll
    for (int b = 0; b < 8; b++) {
        if (d < DDIM - t) v[b] = x0[b * DDIM + d + t];
        else              v[b] = g_tokf[(size_t)(d + t - DDIM) * BATCH + b];
    }

    // ---- pass 1: mean ----
    float r[8];
#pragma unroll
    for (int b = 0; b < 8; b++) r[b] = v[b];
#pragma unroll
    for (int off = 16; off; off >>= 1)
#pragma unroll
        for (int b = 0; b < 8; b++) r[b] += __shfl_down_sync(0xFFFFFFFFu, r[b], off);
    if (lane == 0)
#pragma unroll
        for (int b = 0; b < 8; b++) s_red[wid][b] = r[b];
    __syncthreads();
    if (d < 32) {
        float w[8];
#pragma unroll
        for (int b = 0; b < 8; b++) w[b] = s_red[d][b];
#pragma unroll
        for (int off = 16; off; off >>= 1)
#pragma unroll
            for (int b = 0; b < 8; b++) w[b] += __shfl_down_sync(0xFFFFFFFFu, w[b], off);
        if (d == 0)
#pragma unroll
            for (int b = 0; b < 8; b++) s_bcast[b] = w[b] * (1.0f / DDIM);
    }
    __syncthreads();
    float mu[8];
#pragma unroll
    for (int b = 0; b < 8; b++) mu[b] = s_bcast[b];
    __syncthreads();

    // ---- pass 2: variance ----
#pragma unroll
    for (int b = 0; b < 8; b++) { float dv = v[b] - mu[b]; r[b] = dv * dv; }
#pragma unroll
    for (int off = 16; off; off >>= 1)
#pragma unroll
        for (int b = 0; b < 8; b++) r[b] += __shfl_down_sync(0xFFFFFFFFu, r[b], off);
    if (lane == 0)
#pragma unroll
        for (int b = 0; b < 8; b++) s_red[wid][b] = r[b];
    __syncthreads();
    if (d < 32) {
        float w[8];
#pragma unroll
        for (int b = 0; b < 8; b++) w[b] = s_red[d][b];
#pragma unroll
        for (int off = 16; off; off >>= 1)
#pragma unroll
            for (int b = 0; b < 8; b++) w[b] += __shfl_down_sync(0xFFFFFFFFu, w[b], off);
        if (d == 0)
#pragma unroll
            for (int b = 0; b < 8; b++) {
                float var = w[b] * (1.0f / DDIM);
                s_bcast[b] = 1.0f / sqrtf(var + 1e-5f);
            }
    }
    __syncthreads();
    float xn[8];
#pragma unroll
    for (int b = 0; b < 8; b++) xn[b] = (v[b] - mu[b]) * s_bcast[b];
    __syncthreads();

    // ---- pass 3: max |xn| ----
#pragma unroll
    for (int b = 0; b < 8; b++) r[b] = fabsf(xn[b]);
#pragma unroll
    for (int off = 16; off; off >>= 1)
#pragma unroll
        for (int b = 0; b < 8; b++) r[b] = fmaxf(r[b], __shfl_down_sync(0xFFFFFFFFu, r[b], off));
    if (lane == 0)
#pragma unroll
        for (int b = 0; b < 8; b++) s_red[wid][b] = r[b];
    __syncthreads();
    if (d < 32) {
        float w[8];
#pragma unroll
        for (int b = 0; b < 8; b++) w[b] = s_red[d][b];
#pragma unroll
        for (int off = 16; off; off >>= 1)
#pragma unroll
            for (int b = 0; b < 8; b++) w[b] = fmaxf(w[b], __shfl_down_sync(0xFFFFFFFFu, w[b], off));
        if (d == 0)
#pragma unroll
            for (int b = 0; b < 8; b++) s_bcast[b] = 127.0f / fmaxf(w[b], 1e-5f);
    }
    __syncthreads();

    // ---- quantize + store transposed ----
#pragma unroll
    for (int b = 0; b < 8; b++) {
        float as = s_bcast[b];
        float q  = rintf(fminf(fmaxf(xn[b] * as, -127.0f), 127.0f));
        g_xqT[(size_t)d * BATCH + b] = q / as;
    }
}

// ---------------------------------------------------------------------------
// Kernel 3: matmul + fused gumbel-argmax partial reduce.
// logits[t][b][v] = sum_d xq[b][d] * (k[v][d]-32768) * scale/32768
// 128 blocks x 256 threads; each block covers 128 vocab rows.
// ---------------------------------------------------------------------------
__global__ void __launch_bounds__(256) matmul_kernel(int t, const float* __restrict__ scales,
                                                     float* __restrict__ d_out,
                                                     unsigned skx, unsigned sky) {
    __shared__ float s_xq[DDIM * BATCH];            // [d][b], 32 KB
    __shared__ float s_lg[128 * BATCH];             // block's logits [v_local][b], 4 KB
    __shared__ unsigned long long s_wbest[8][4];    // per-warp best keys

    for (int i = threadIdx.x; i < DDIM * BATCH / 4; i += blockDim.x)
        reinterpret_cast<float4*>(s_xq)[i] = reinterpret_cast<const float4*>(g_xqT)[i];
    __syncthreads();

    const int l    = t & 3;
    const int warp = threadIdx.x >> 5;
    const int lane = threadIdx.x & 31;
    const int g    = lane >> 3;
    const int j    = lane & 7;
    const int v0   = blockIdx.x * 128 + warp * 16 + g * 4;

    const uint4* wrow = reinterpret_cast<const uint4*>(
        g_wk + ((size_t)l * VOCAB + v0) * DDIM);   // 128 uint4 per row

    float acc[4][8];
#pragma unroll
    for (int r = 0; r < 4; r++)
#pragma unroll
        for (int b = 0; b < 8; b++) acc[r][b] = 0.0f;

#pragma unroll 4
    for (int m = 0; m < 16; m++) {
        const int c = j + 8 * m;                 // uint4 index within row
        uint4 u0 = wrow[c];
        uint4 u1 = wrow[c + 128];
        uint4 u2 = wrow[c + 256];
        uint4 u3 = wrow[c + 384];
        unsigned w[4][4] = {
            {u0.x, u0.y, u0.z, u0.w},
            {u1.x, u1.y, u1.z, u1.w},
            {u2.x, u2.y, u2.z, u2.w},
            {u3.x, u3.y, u3.z, u3.w},
        };
        const int dbase = c * 8;
#pragma unroll
        for (int e = 0; e < 8; e++) {
            const float4 xa = *reinterpret_cast<const float4*>(&s_xq[(dbase + e) * BATCH]);
            const float4 xb = *reinterpret_cast<const float4*>(&s_xq[(dbase + e) * BATCH + 4]);
            const unsigned sel = (e & 1) ? 0x7432u : 0x7410u;
#pragma unroll
            for (int r = 0; r < 4; r++) {
                // f = 2^23 + k  (exact), then k - 32768 via one FADD
                float wf = __uint_as_float(__byte_perm(w[r][e >> 1], 0x4B000000u, sel))
                           - 8421376.0f;
                acc[r][0] += wf * xa.x;
                acc[r][1] += wf * xa.y;
                acc[r][2] += wf * xa.z;
                acc[r][3] += wf * xa.w;
                acc[r][4] += wf * xb.x;
                acc[r][5] += wf * xb.y;
                acc[r][6] += wf * xb.z;
                acc[r][7] += wf * xb.w;
            }
        }
    }

    // reduce over the 8 D-slice lanes (groups of 8 within the warp)
#pragma unroll
    for (int r = 0; r < 4; r++)
#pragma unroll
        for (int b = 0; b < 8; b++) {
            float a = acc[r][b];
            a += __shfl_down_sync(0xFFFFFFFFu, a, 4, 8);
            a += __shfl_down_sync(0xFFFFFFFFu, a, 2, 8);
            a += __shfl_down_sync(0xFFFFFFFFu, a, 1, 8);
            acc[r][b] = a;
        }

    const float cl = scales[l] * (1.0f / 32768.0f);
    if (j == 0) {
#pragma unroll
        for (int r = 0; r < 4; r++) {
            const int vl = warp * 16 + g * 4 + r;
            const int v  = blockIdx.x * 128 + vl;
#pragma unroll
            for (int b = 0; b < 8; b++) {
                float lgv = acc[r][b] * cl;
                d_out[TOKS_COUNT + ((size_t)t * BATCH + b) * VOCAB + v] = lgv;
                s_lg[vl * BATCH + b] = lgv;
            }
        }
    }
    __syncthreads();

    // ---- fused gumbel + block argmax ----
    // thread tid: v_local = tid & 127, bg = tid >> 7; handles b = bg*4 .. bg*4+3
    {
        const int v_local = threadIdx.x & 127;
        const int bg      = threadIdx.x >> 7;
        const int v       = blockIdx.x * 128 + v_local;
        uint2 sk; sk.x = skx; sk.y = sky;

        unsigned long long key[4];
#pragma unroll
        for (int i = 0; i < 4; i++) {
            const int b = bg * 4 + i;
            const unsigned ctr = (unsigned)b * (unsigned)VOCAB + (unsigned)v;
            uint2 rr = threefry2x32(sk, 0u, ctr);
            unsigned bits = rr.x ^ rr.y;
            float u01 = __uint_as_float((bits >> 9) | 0x3f800000u) - 1.0f;
            float u   = fmaxf(u01, 1.17549435e-38f);
            float gum = -logf(-logf(u));
            float val = s_lg[v_local * BATCH + b] + gum;
            key[i] = ((unsigned long long)orderf(val) << 32)
                   | (unsigned long long)(0xFFFFFFFFu - (unsigned)v);
        }
        // warp-reduce max (32 lanes span 32 v values, same bg)
#pragma unroll
        for (int off = 16; off; off >>= 1)
#pragma unroll
            for (int i = 0; i < 4; i++) {
                unsigned long long o = __shfl_down_sync(0xFFFFFFFFu, key[i], off);
                if (o > key[i]) key[i] = o;
            }
        if (lane == 0)
#pragma unroll
            for (int i = 0; i < 4; i++) s_wbest[warp][i] = key[i];
    }
    __syncthreads();

    // warp 0 merges 8 warps x 4 keys -> 8 per-b bests -> atomicMax
    if (warp == 0) {
        const int b     = lane >> 2;      // 0..7
        const int wslot = lane & 3;       // 0..3
        const int w     = (b >> 2) * 4 + wslot;
        const int i     = b & 3;
        unsigned long long key = s_wbest[w][i];
#pragma unroll
        for (int off = 2; off; off >>= 1) {
            unsigned long long o = __shfl_down_sync(0xFFFFFFFFu, key, off, 4);
            if (o > key) key = o;
        }
        if (wslot == 0) atomicMax(&g_best[b], key);
    }
}

// ---------------------------------------------------------------------------
// Kernel 4: final token decode for step T-1
// ---------------------------------------------------------------------------
__global__ void finalize_kernel(float* __restrict__ d_out) {
    int b = threadIdx.x;
    if (b < BATCH) {
        unsigned long long k = g_best[b];
        unsigned idx = 0xFFFFFFFFu - (unsigned)(k & 0xFFFFFFFFu);
        float tokf = (float)idx;
        g_tokf[(size_t)(TSTEPS - 1) * BATCH + b] = tokf;
        d_out[(size_t)(TSTEPS - 1) * BATCH + b]  = tokf;
    }
}

// ---------------------------------------------------------------------------
// Launch
// ---------------------------------------------------------------------------
extern "C" void kernel_launch(void* const* d_in, const int* in_sizes, int n_in,
                              void* d_out, int out_size) {
    const float* x0     = (const float*)d_in[0];   // [8,1024]
    const int*   seeds  = (const int*)d_in[1];     // [4,65536]
    const float* scales = (const float*)d_in[2];   // [4]
    float* out = (float*)d_out;

    // host-side subkey chain (input-independent, deterministic):
    // key_0 = key(1) = (0,1); each step: new_key = tf(key,0,0), sk = tf(key,0,1)
    unsigned skx[TSTEPS], sky[TSTEPS];
    {
        uint2 key; key.x = 0u; key.y = 1u;
        for (int t = 0; t < TSTEPS; t++) {
            uint2 nk = threefry2x32(key, 0u, 0u);
            uint2 sk = threefry2x32(key, 0u, 1u);
            skx[t] = sk.x; sky[t] = sk.y;
            key = nk;
        }
    }

    decompress_kernel<<<NSEEDS_TOT / 256, 256>>>(seeds);

    for (int t = 0; t < TSTEPS; t++) {
        prep_kernel<<<1, 1024>>>(x0, t, out);
        matmul_kernel<<<VOCAB / 128, 256>>>(t, scales, out, skx[t], sky[t]);
    }
    finalize_kernel<<<1, 32>>>(out);
}

// round 5
// speedup vs baseline: 1.6481x; 1.1269x over previous
#include <cuda_runtime.h>
#include <cstdint>
#include <cstddef>

// ---------------------------------------------------------------------------
// Problem constants
// ---------------------------------------------------------------------------
#define VOCAB   16384
#define DDIM    1024
#define BATCH   8
#define TSTEPS  16
#define NLAYERS 4
#define LFSR_POLY 0x100Bu           // 69643 & 0xFFFF (bits 0,1,3,12)
#define SEEDS_PER_LAYER 65536       // VOCAB*DDIM/256
#define BLOCK_VALS 256
#define NSEEDS_TOT (NLAYERS * SEEDS_PER_LAYER)   // 262144

// toks [T,B] (as float) followed by logits [T,B,V] in d_out (float32)
#define TOKS_COUNT (TSTEPS*BATCH)

// ---------------------------------------------------------------------------
// Device scratch (static globals: allocation-free)
// ---------------------------------------------------------------------------
__device__ unsigned short g_wk[(size_t)NLAYERS * VOCAB * DDIM];  // 128 MB raw LFSR states
__device__ unsigned long long g_bestA[TSTEPS * BATCH];  // per-step packed (ordered_val<<32)|(~v)

// ---------------------------------------------------------------------------
// threefry2x32-20 (exact JAX implementation), host+device
// ---------------------------------------------------------------------------
__host__ __device__ __forceinline__ unsigned rotl32(unsigned x, int r) {
#ifdef __CUDA_ARCH__
    return __funnelshift_l(x, x, r);
#else
    return (x << r) | (x >> (32 - r));
#endif
}

__host__ __device__ __forceinline__ uint2 threefry2x32(uint2 key, unsigned c0, unsigned c1) {
    unsigned ks0 = key.x, ks1 = key.y;
    unsigned ks2 = ks0 ^ ks1 ^ 0x1BD11BDAu;
    unsigned x0 = c0 + ks0;
    unsigned x1 = c1 + ks1;
#define TF_R4(a,b,c,d)                                              \
    x0 += x1; x1 = rotl32(x1,(a)); x1 ^= x0;                        \
    x0 += x1; x1 = rotl32(x1,(b)); x1 ^= x0;                        \
    x0 += x1; x1 = rotl32(x1,(c)); x1 ^= x0;                        \
    x0 += x1; x1 = rotl32(x1,(d)); x1 ^= x0;
    TF_R4(13,15,26,6);   x0 += ks1; x1 += ks2 + 1u;
    TF_R4(17,29,16,24);  x0 += ks2; x1 += ks0 + 2u;
    TF_R4(13,15,26,6);   x0 += ks0; x1 += ks1 + 3u;
    TF_R4(17,29,16,24);  x0 += ks1; x1 += ks2 + 4u;
    TF_R4(13,15,26,6);   x0 += ks2; x1 += ks0 + 5u;
#undef TF_R4
    uint2 out; out.x = x0; out.y = x1; return out;
}

// ordered-uint encoding of float for monotone unsigned compare
__device__ __forceinline__ unsigned orderf(float f) {
    unsigned u = __float_as_uint(f);
    return (u & 0x80000000u) ? ~u : (u | 0x80000000u);
}

__device__ __forceinline__ float decode_tok(unsigned long long k) {
    return (float)(0xFFFFFFFFu - (unsigned)(k & 0xFFFFFFFFu));
}

// ---------------------------------------------------------------------------
// Kernel 1: LFSR decompression -> raw uint16 states, one thread per seed.
// Also zeroes g_bestA (runs first in every graph replay -> deterministic).
// ---------------------------------------------------------------------------
__global__ void decompress_kernel(const int* __restrict__ seeds) {
    int sid = blockIdx.x * blockDim.x + threadIdx.x;   // 0 .. 262143
    if (sid < TSTEPS * BATCH) g_bestA[sid] = 0ull;
    unsigned state = ((unsigned)seeds[sid]) & 0xFFFFu;
    uint4* out = reinterpret_cast<uint4*>(g_wk + (size_t)sid * BLOCK_VALS);
#pragma unroll 4
    for (int m = 0; m < 32; m++) {
        unsigned short v[8];
#pragma unroll
        for (int e = 0; e < 8; e++) {
            v[e] = (unsigned short)state;
            unsigned fb = __popc(state & LFSR_POLY) & 1u;
            state = ((state >> 1) | (fb << 15)) & 0xFFFFu;
        }
        uint4 u;
        u.x = (unsigned)v[0] | ((unsigned)v[1] << 16);
        u.y = (unsigned)v[2] | ((unsigned)v[3] << 16);
        u.z = (unsigned)v[4] | ((unsigned)v[5] << 16);
        u.w = (unsigned)v[6] | ((unsigned)v[7] << 16);
        out[m] = u;
    }
}

// ---------------------------------------------------------------------------
// Kernel 2: fused step kernel.
//   (a) inline prep: rolling buffer (tokens decoded from g_bestA[s<t]) +
//       layernorm + quantize, redundantly per block -> s_xq
//   (b) matmul: logits[t][b][v] = sum_d xq[b][d]*(k[v][d]-32768)*scale/32768
//   (c) fused gumbel-argmax partial reduce -> atomicMax g_bestA[t]
// 128 blocks x 256 threads; each block covers 128 vocab rows.
// ---------------------------------------------------------------------------
__global__ void __launch_bounds__(256) step_kernel(int t, const float* __restrict__ scales,
                                                   float* __restrict__ d_out,
                                                   unsigned skx, unsigned sky,
                                                   const float* __restrict__ x0) {
    __shared__ float s_xq[DDIM * BATCH];            // [d][b], 32 KB
    __shared__ float s_lg[128 * BATCH];             // block's logits [v_local][b], 4 KB
    __shared__ float s_red[8][8];                   // per-warp partials per b
    __shared__ float s_bc[8];
    __shared__ unsigned long long s_wbest[8][4];    // per-warp best keys

    const int tid  = threadIdx.x;
    const int warp = tid >> 5;
    const int lane = tid & 31;

    // ================= inline prep =================
    float v[4][8];
#pragma unroll
    for (int k = 0; k < 4; k++) {
        const int d = tid + 256 * k;
        if (d < DDIM - t) {
#pragma unroll
            for (int b = 0; b < 8; b++) v[k][b] = x0[b * DDIM + d + t];
        } else {
            const int s = d + t - DDIM;   // 0..t-1
#pragma unroll
            for (int b = 0; b < 8; b++) v[k][b] = decode_tok(g_bestA[s * BATCH + b]);
        }
    }

    // ---- mean ----
    float part[8];
#pragma unroll
    for (int b = 0; b < 8; b++)
        part[b] = v[0][b] + v[1][b] + v[2][b] + v[3][b];
#pragma unroll
    for (int off = 16; off; off >>= 1)
#pragma unroll
        for (int b = 0; b < 8; b++) part[b] += __shfl_down_sync(0xFFFFFFFFu, part[b], off);
    if (lane == 0)
#pragma unroll
        for (int b = 0; b < 8; b++) s_red[warp][b] = part[b];
    __syncthreads();
    if (warp == 0 && lane < 8) {
        const int b = lane;
        float s = 0.0f;
#pragma unroll
        for (int w = 0; w < 8; w++) s += s_red[w][b];
        s_bc[b] = s * (1.0f / DDIM);
    }
    __syncthreads();
    float mu[8];
#pragma unroll
    for (int b = 0; b < 8; b++) mu[b] = s_bc[b];
    __syncthreads();

    // ---- variance ----
#pragma unroll
    for (int b = 0; b < 8; b++) {
        float d0 = v[0][b] - mu[b], d1 = v[1][b] - mu[b];
        float d2 = v[2][b] - mu[b], d3 = v[3][b] - mu[b];
        part[b] = d0 * d0 + d1 * d1 + d2 * d2 + d3 * d3;
    }
#pragma unroll
    for (int off = 16; off; off >>= 1)
#pragma unroll
        for (int b = 0; b < 8; b++) part[b] += __shfl_down_sync(0xFFFFFFFFu, part[b], off);
    if (lane == 0)
#pragma unroll
        for (int b = 0; b < 8; b++) s_red[warp][b] = part[b];
    __syncthreads();
    if (warp == 0 && lane < 8) {
        const int b = lane;
        float s = 0.0f;
#pragma unroll
        for (int w = 0; w < 8; w++) s += s_red[w][b];
        s_bc[b] = 1.0f / sqrtf(s * (1.0f / DDIM) + 1e-5f);
    }
    __syncthreads();
    float xn[4][8];
#pragma unroll
    for (int k = 0; k < 4; k++)
#pragma unroll
        for (int b = 0; b < 8; b++) xn[k][b] = (v[k][b] - mu[b]) * s_bc[b];
    __syncthreads();

    // ---- max |xn| ----
#pragma unroll
    for (int b = 0; b < 8; b++)
        part[b] = fmaxf(fmaxf(fabsf(xn[0][b]), fabsf(xn[1][b])),
                        fmaxf(fabsf(xn[2][b]), fabsf(xn[3][b])));
#pragma unroll
    for (int off = 16; off; off >>= 1)
#pragma unroll
        for (int b = 0; b < 8; b++) part[b] = fmaxf(part[b], __shfl_down_sync(0xFFFFFFFFu, part[b], off));
    if (lane == 0)
#pragma unroll
        for (int b = 0; b < 8; b++) s_red[warp][b] = part[b];
    __syncthreads();
    if (warp == 0 && lane < 8) {
        const int b = lane;
        float s = s_red[0][b];
#pragma unroll
        for (int w = 1; w < 8; w++) s = fmaxf(s, s_red[w][b]);
        s_bc[b] = 127.0f / fmaxf(s, 1e-5f);
    }
    __syncthreads();

    // ---- quantize -> s_xq[d*8+b] ----
#pragma unroll
    for (int k = 0; k < 4; k++) {
        const int d = tid + 256 * k;
#pragma unroll
        for (int b = 0; b < 8; b++) {
            float as = s_bc[b];
            float q  = rintf(fminf(fmaxf(xn[k][b] * as, -127.0f), 127.0f));
            s_xq[d * BATCH + b] = q / as;
        }
    }
    __syncthreads();

    // ================= matmul =================
    const int l  = t & 3;
    const int g  = lane >> 3;
    const int j  = lane & 7;
    const int v0 = blockIdx.x * 128 + warp * 16 + g * 4;

    const uint4* wrow = reinterpret_cast<const uint4*>(
        g_wk + ((size_t)l * VOCAB + v0) * DDIM);   // 128 uint4 per row

    float acc[4][8];
#pragma unroll
    for (int r = 0; r < 4; r++)
#pragma unroll
        for (int b = 0; b < 8; b++) acc[r][b] = 0.0f;

#pragma unroll 4
    for (int m = 0; m < 16; m++) {
        const int c = j + 8 * m;                 // uint4 index within row
        uint4 u0 = wrow[c];
        uint4 u1 = wrow[c + 128];
        uint4 u2 = wrow[c + 256];
        uint4 u3 = wrow[c + 384];
        unsigned w[4][4] = {
            {u0.x, u0.y, u0.z, u0.w},
            {u1.x, u1.y, u1.z, u1.w},
            {u2.x, u2.y, u2.z, u2.w},
            {u3.x, u3.y, u3.z, u3.w},
        };
        const int dbase = c * 8;
#pragma unroll
        for (int e = 0; e < 8; e++) {
            const float4 xa = *reinterpret_cast<const float4*>(&s_xq[(dbase + e) * BATCH]);
            const float4 xb = *reinterpret_cast<const float4*>(&s_xq[(dbase + e) * BATCH + 4]);
            const unsigned sel = (e & 1) ? 0x7432u : 0x7410u;
#pragma unroll
            for (int r = 0; r < 4; r++) {
                // f = 2^23 + k  (exact), then k - 32768 via one FADD
                float wf = __uint_as_float(__byte_perm(w[r][e >> 1], 0x4B000000u, sel))
                           - 8421376.0f;
                acc[r][0] += wf * xa.x;
                acc[r][1] += wf * xa.y;
                acc[r][2] += wf * xa.z;
                acc[r][3] += wf * xa.w;
                acc[r][4] += wf * xb.x;
                acc[r][5] += wf * xb.y;
                acc[r][6] += wf * xb.z;
                acc[r][7] += wf * xb.w;
            }
        }
    }

    // reduce over the 8 D-slice lanes (groups of 8 within the warp)
#pragma unroll
    for (int r = 0; r < 4; r++)
#pragma unroll
        for (int b = 0; b < 8; b++) {
            float a = acc[r][b];
            a += __shfl_down_sync(0xFFFFFFFFu, a, 4, 8);
            a += __shfl_down_sync(0xFFFFFFFFu, a, 2, 8);
            a += __shfl_down_sync(0xFFFFFFFFu, a, 1, 8);
            acc[r][b] = a;
        }

    const float cl = scales[l] * (1.0f / 32768.0f);
    if (j == 0) {
#pragma unroll
        for (int r = 0; r < 4; r++) {
            const int vl = warp * 16 + g * 4 + r;
            const int vg = blockIdx.x * 128 + vl;
#pragma unroll
            for (int b = 0; b < 8; b++) {
                float lgv = acc[r][b] * cl;
                d_out[TOKS_COUNT + ((size_t)t * BATCH + b) * VOCAB + vg] = lgv;
                s_lg[vl * BATCH + b] = lgv;
            }
        }
    }
    __syncthreads();

    // ================= fused gumbel + block argmax =================
    {
        const int v_local = tid & 127;
        const int bg      = tid >> 7;
        const int vg      = blockIdx.x * 128 + v_local;
        uint2 sk; sk.x = skx; sk.y = sky;

        unsigned long long key[4];
#pragma unroll
        for (int i = 0; i < 4; i++) {
            const int b = bg * 4 + i;
            const unsigned ctr = (unsigned)b * (unsigned)VOCAB + (unsigned)vg;
            uint2 rr = threefry2x32(sk, 0u, ctr);
            unsigned bits = rr.x ^ rr.y;
            float u01 = __uint_as_float((bits >> 9) | 0x3f800000u) - 1.0f;
            float u   = fmaxf(u01, 1.17549435e-38f);
            float gum = -logf(-logf(u));
            float val = s_lg[v_local * BATCH + b] + gum;
            key[i] = ((unsigned long long)orderf(val) << 32)
                   | (unsigned long long)(0xFFFFFFFFu - (unsigned)vg);
        }
#pragma unroll
        for (int off = 16; off; off >>= 1)
#pragma unroll
            for (int i = 0; i < 4; i++) {
                unsigned long long o = __shfl_down_sync(0xFFFFFFFFu, key[i], off);
                if (o > key[i]) key[i] = o;
            }
        if (lane == 0)
#pragma unroll
            for (int i = 0; i < 4; i++) s_wbest[warp][i] = key[i];
    }
    __syncthreads();

    // warp 0 merges 8 warps x 4 keys -> 8 per-b bests -> atomicMax
    if (warp == 0) {
        const int b     = lane >> 2;      // 0..7
        const int wslot = lane & 3;       // 0..3
        const int w     = (b >> 2) * 4 + wslot;
        const int i     = b & 3;
        unsigned long long key = s_wbest[w][i];
#pragma unroll
        for (int off = 2; off; off >>= 1) {
            unsigned long long o = __shfl_down_sync(0xFFFFFFFFu, key, off, 4);
            if (o > key) key = o;
        }
        if (wslot == 0) atomicMax(&g_bestA[t * BATCH + b], key);
    }
}

// ---------------------------------------------------------------------------
// Kernel 3: final token decode for all steps
// ---------------------------------------------------------------------------
__global__ void finalize_kernel(float* __restrict__ d_out) {
    int i = threadIdx.x;
    if (i < TSTEPS * BATCH) d_out[i] = decode_tok(g_bestA[i]);
}

// ---------------------------------------------------------------------------
// Launch
// ---------------------------------------------------------------------------
extern "C" void kernel_launch(void* const* d_in, const int* in_sizes, int n_in,
                              void* d_out, int out_size) {
    const float* x0     = (const float*)d_in[0];   // [8,1024]
    const int*   seeds  = (const int*)d_in[1];     // [4,65536]
    const float* scales = (const float*)d_in[2];   // [4]
    float* out = (float*)d_out;

    // host-side subkey chain (input-independent, deterministic):
    // key_0 = key(1) = (0,1); each step: new_key = tf(key,0,0), sk = tf(key,0,1)
    unsigned skx[TSTEPS], sky[TSTEPS];
    {
        uint2 key; key.x = 0u; key.y = 1u;
        for (int t = 0; t < TSTEPS; t++) {
            uint2 nk = threefry2x32(key, 0u, 0u);
            uint2 sk = threefry2x32(key, 0u, 1u);
            skx[t] = sk.x; sky[t] = sk.y;
            key = nk;
        }
    }

    decompress_kernel<<<NSEEDS_TOT / 256, 256>>>(seeds);

    for (int t = 0; t < TSTEPS; t++) {
        step_kernel<<<VOCAB / 128, 256>>>(t, scales, out, skx[t], sky[t], x0);
    }
    finalize_kernel<<<1, 128>>>(out);
}

// round 6
// speedup vs baseline: 3.0692x; 1.8623x over previous
#include <cuda_runtime.h>
#include <cstdint>
#include <cstddef>

// ---------------------------------------------------------------------------
// Problem constants
// ---------------------------------------------------------------------------
#define VOCAB   16384
#define DDIM    1024
#define BATCH   8
#define TSTEPS  16
#define NLAYERS 4
#define LFSR_POLY 0x100Bu           // 69643 & 0xFFFF (bits 0,1,3,12)
#define SEEDS_PER_LAYER 65536       // VOCAB*DDIM/256
#define BLOCK_VALS 256
#define NSEEDS_TOT (NLAYERS * SEEDS_PER_LAYER)   // 262144

// toks [T,B] (as float) followed by logits [T,B,V] in d_out (float32)
#define TOKS_COUNT (TSTEPS*BATCH)

#define NTHREADS 512
#define NWARPS   16

// ---------------------------------------------------------------------------
// Device scratch (static globals: allocation-free)
// ---------------------------------------------------------------------------
__device__ unsigned short g_wk[(size_t)NLAYERS * VOCAB * DDIM];  // 128 MB raw LFSR states
__device__ unsigned long long g_bestA[TSTEPS * BATCH];  // per-step packed (ordered_val<<32)|(~v)

// ---------------------------------------------------------------------------
// threefry2x32-20 (exact JAX implementation), host+device
// ---------------------------------------------------------------------------
__host__ __device__ __forceinline__ unsigned rotl32(unsigned x, int r) {
#ifdef __CUDA_ARCH__
    return __funnelshift_l(x, x, r);
#else
    return (x << r) | (x >> (32 - r));
#endif
}

__host__ __device__ __forceinline__ uint2 threefry2x32(uint2 key, unsigned c0, unsigned c1) {
    unsigned ks0 = key.x, ks1 = key.y;
    unsigned ks2 = ks0 ^ ks1 ^ 0x1BD11BDAu;
    unsigned x0 = c0 + ks0;
    unsigned x1 = c1 + ks1;
#define TF_R4(a,b,c,d)                                              \
    x0 += x1; x1 = rotl32(x1,(a)); x1 ^= x0;                        \
    x0 += x1; x1 = rotl32(x1,(b)); x1 ^= x0;                        \
    x0 += x1; x1 = rotl32(x1,(c)); x1 ^= x0;                        \
    x0 += x1; x1 = rotl32(x1,(d)); x1 ^= x0;
    TF_R4(13,15,26,6);   x0 += ks1; x1 += ks2 + 1u;
    TF_R4(17,29,16,24);  x0 += ks2; x1 += ks0 + 2u;
    TF_R4(13,15,26,6);   x0 += ks0; x1 += ks1 + 3u;
    TF_R4(17,29,16,24);  x0 += ks1; x1 += ks2 + 4u;
    TF_R4(13,15,26,6);   x0 += ks2; x1 += ks0 + 5u;
#undef TF_R4
    uint2 out; out.x = x0; out.y = x1; return out;
}

// ordered-uint encoding of float for monotone unsigned compare
__device__ __forceinline__ unsigned orderf(float f) {
    unsigned u = __float_as_uint(f);
    return (u & 0x80000000u) ? ~u : (u | 0x80000000u);
}

__device__ __forceinline__ float decode_tok(unsigned long long k) {
    return (float)(0xFFFFFFFFu - (unsigned)(k & 0xFFFFFFFFu));
}

// packed f32x2 fma: acc = a*b + acc  (two independent fp32 FMAs, RN)
__device__ __forceinline__ void ffma2(unsigned long long& acc,
                                      unsigned long long a, unsigned long long b) {
    asm("fma.rn.f32x2 %0, %1, %2, %0;" : "+l"(acc) : "l"(a), "l"(b));
}
__device__ __forceinline__ unsigned long long pack_dup(float f) {
    unsigned long long r;
    unsigned u = __float_as_uint(f);
    asm("mov.b64 %0, {%1, %1};" : "=l"(r) : "r"(u));
    return r;
}
__device__ __forceinline__ void unpack2(unsigned long long p, float& lo, float& hi) {
    unsigned a, b;
    asm("mov.b64 {%0, %1}, %2;" : "=r"(a), "=r"(b) : "l"(p));
    lo = __uint_as_float(a); hi = __uint_as_float(b);
}

// xq smem slot swizzle: conflict-free for both store (d=lane-adjacent) and
// matmul load (d = j*8 + 64m + e -> offset j*128 + (e^j)*16 bytes)
__device__ __forceinline__ int xq_slot(int d) { return d ^ ((d >> 3) & 7); }

// ---------------------------------------------------------------------------
// Kernel 1: LFSR decompression -> raw uint16 states, one thread per seed.
// Also zeroes g_bestA (runs first in every graph replay -> deterministic).
// ---------------------------------------------------------------------------
__global__ void decompress_kernel(const int* __restrict__ seeds) {
    int sid = blockIdx.x * blockDim.x + threadIdx.x;   // 0 .. 262143
    if (sid < TSTEPS * BATCH) g_bestA[sid] = 0ull;
    unsigned state = ((unsigned)seeds[sid]) & 0xFFFFu;
    uint4* out = reinterpret_cast<uint4*>(g_wk + (size_t)sid * BLOCK_VALS);
#pragma unroll 4
    for (int m = 0; m < 32; m++) {
        unsigned short v[8];
#pragma unroll
        for (int e = 0; e < 8; e++) {
            v[e] = (unsigned short)state;
            unsigned fb = __popc(state & LFSR_POLY) & 1u;
            state = ((state >> 1) | (fb << 15)) & 0xFFFFu;
        }
        uint4 u;
        u.x = (unsigned)v[0] | ((unsigned)v[1] << 16);
        u.y = (unsigned)v[2] | ((unsigned)v[3] << 16);
        u.z = (unsigned)v[4] | ((unsigned)v[5] << 16);
        u.w = (unsigned)v[6] | ((unsigned)v[7] << 16);
        out[m] = u;
    }
}

// ---------------------------------------------------------------------------
// Kernel 2: fused step kernel. 128 blocks x 512 threads, 128 vocab rows/block.
//   (a) inline prep -> swizzled s_A (b0..3) / s_B (b4..7)
//   (b) matmul with packed f32x2 FMA
//   (c) fused gumbel-argmax -> atomicMax g_bestA[t]
// ---------------------------------------------------------------------------
__global__ void __launch_bounds__(NTHREADS) step_kernel(int t, const float* __restrict__ scales,
                                                        float* __restrict__ d_out,
                                                        unsigned skx, unsigned sky,
                                                        const float* __restrict__ x0) {
    __shared__ float s_A[DDIM * 4];                 // [slot(d)][b0..3], 16 KB
    __shared__ float s_B[DDIM * 4];                 // [slot(d)][b4..7], 16 KB
    __shared__ float s_lg[128 * 9];                 // logits [v_local][b], padded, 4.5 KB
    __shared__ float s_red[NWARPS][8];
    __shared__ float s_bc[8];
    __shared__ unsigned long long s_wbest[NWARPS][2];

    const int tid  = threadIdx.x;
    const int warp = tid >> 5;
    const int lane = tid & 31;

    // ================= inline prep =================
    float v[2][8];
#pragma unroll
    for (int k = 0; k < 2; k++) {
        const int d = tid + NTHREADS * k;
        if (d < DDIM - t) {
#pragma unroll
            for (int b = 0; b < 8; b++) v[k][b] = x0[b * DDIM + d + t];
        } else {
            const int s = d + t - DDIM;   // 0..t-1
#pragma unroll
            for (int b = 0; b < 8; b++) v[k][b] = decode_tok(g_bestA[s * BATCH + b]);
        }
    }

    // ---- mean ----
    float part[8];
#pragma unroll
    for (int b = 0; b < 8; b++) part[b] = v[0][b] + v[1][b];
#pragma unroll
    for (int off = 16; off; off >>= 1)
#pragma unroll
        for (int b = 0; b < 8; b++) part[b] += __shfl_down_sync(0xFFFFFFFFu, part[b], off);
    if (lane == 0)
#pragma unroll
        for (int b = 0; b < 8; b++) s_red[warp][b] = part[b];
    __syncthreads();
    if (warp == 0 && lane < 8) {
        const int b = lane;
        float s = 0.0f;
#pragma unroll
        for (int w = 0; w < NWARPS; w++) s += s_red[w][b];
        s_bc[b] = s * (1.0f / DDIM);
    }
    __syncthreads();
    float mu[8];
#pragma unroll
    for (int b = 0; b < 8; b++) mu[b] = s_bc[b];
    __syncthreads();

    // ---- variance ----
#pragma unroll
    for (int b = 0; b < 8; b++) {
        float d0 = v[0][b] - mu[b], d1 = v[1][b] - mu[b];
        part[b] = d0 * d0 + d1 * d1;
    }
#pragma unroll
    for (int off = 16; off; off >>= 1)
#pragma unroll
        for (int b = 0; b < 8; b++) part[b] += __shfl_down_sync(0xFFFFFFFFu, part[b], off);
    if (lane == 0)
#pragma unroll
        for (int b = 0; b < 8; b++) s_red[warp][b] = part[b];
    __syncthreads();
    if (warp == 0 && lane < 8) {
        const int b = lane;
        float s = 0.0f;
#pragma unroll
        for (int w = 0; w < NWARPS; w++) s += s_red[w][b];
        s_bc[b] = 1.0f / sqrtf(s * (1.0f / DDIM) + 1e-5f);
    }
    __syncthreads();
    float xn[2][8];
#pragma unroll
    for (int k = 0; k < 2; k++)
#pragma unroll
        for (int b = 0; b < 8; b++) xn[k][b] = (v[k][b] - mu[b]) * s_bc[b];
    __syncthreads();

    // ---- max |xn| ----
#pragma unroll
    for (int b = 0; b < 8; b++) part[b] = fmaxf(fabsf(xn[0][b]), fabsf(xn[1][b]));
#pragma unroll
    for (int off = 16; off; off >>= 1)
#pragma unroll
        for (int b = 0; b < 8; b++) part[b] = fmaxf(part[b], __shfl_down_sync(0xFFFFFFFFu, part[b], off));
    if (lane == 0)
#pragma unroll
        for (int b = 0; b < 8; b++) s_red[warp][b] = part[b];
    __syncthreads();
    if (warp == 0 && lane < 8) {
        const int b = lane;
        float s = s_red[0][b];
#pragma unroll
        for (int w = 1; w < NWARPS; w++) s = fmaxf(s, s_red[w][b]);
        s_bc[b] = 127.0f / fmaxf(s, 1e-5f);
    }
    __syncthreads();

    // ---- quantize -> swizzled s_A / s_B ----
#pragma unroll
    for (int k = 0; k < 2; k++) {
        const int d  = tid + NTHREADS * k;
        const int sl = xq_slot(d);
        float4 qa, qb;
        {
            float as0 = s_bc[0], as1 = s_bc[1], as2 = s_bc[2], as3 = s_bc[3];
            qa.x = rintf(fminf(fmaxf(xn[k][0] * as0, -127.0f), 127.0f)) / as0;
            qa.y = rintf(fminf(fmaxf(xn[k][1] * as1, -127.0f), 127.0f)) / as1;
            qa.z = rintf(fminf(fmaxf(xn[k][2] * as2, -127.0f), 127.0f)) / as2;
            qa.w = rintf(fminf(fmaxf(xn[k][3] * as3, -127.0f), 127.0f)) / as3;
            float as4 = s_bc[4], as5 = s_bc[5], as6 = s_bc[6], as7 = s_bc[7];
            qb.x = rintf(fminf(fmaxf(xn[k][4] * as4, -127.0f), 127.0f)) / as4;
            qb.y = rintf(fminf(fmaxf(xn[k][5] * as5, -127.0f), 127.0f)) / as5;
            qb.z = rintf(fminf(fmaxf(xn[k][6] * as6, -127.0f), 127.0f)) / as6;
            qb.w = rintf(fminf(fmaxf(xn[k][7] * as7, -127.0f), 127.0f)) / as7;
        }
        *reinterpret_cast<float4*>(&s_A[sl * 4]) = qa;
        *reinterpret_cast<float4*>(&s_B[sl * 4]) = qb;
    }
    __syncthreads();

    // ================= matmul =================
    // warp covers 8 rows; lane (g, j): g = lane>>3 -> 2 rows, j = lane&7 -> d-slice
    const int l  = t & 3;
    const int g  = lane >> 3;
    const int j  = lane & 7;
    const int vl0 = warp * 8 + g * 2;              // local row of first of 2 rows
    const int v0  = blockIdx.x * 128 + vl0;

    const uint4* wrow = reinterpret_cast<const uint4*>(
        g_wk + ((size_t)l * VOCAB + v0) * DDIM);   // 128 uint4 per row; row stride 128 uint4

    unsigned long long acc[2][4];
#pragma unroll
    for (int r = 0; r < 2; r++)
#pragma unroll
        for (int i = 0; i < 4; i++) acc[r][i] = 0ull;

#pragma unroll 4
    for (int m = 0; m < 16; m++) {
        const int c = j + 8 * m;                 // uint4 index within row
        uint4 u0 = wrow[c];
        uint4 u1 = wrow[c + 128];
        unsigned w[2][4] = {
            {u0.x, u0.y, u0.z, u0.w},
            {u1.x, u1.y, u1.z, u1.w},
        };
        const int xbase = (j * 8 + 64 * m);      // d-base (low 3 bits zero)
        const ulonglong2* Arow = reinterpret_cast<const ulonglong2*>(&s_A[xbase * 4]);
        const ulonglong2* Brow = reinterpret_cast<const ulonglong2*>(&s_B[xbase * 4]);
#pragma unroll
        for (int e = 0; e < 8; e++) {
            const int sl = e ^ j;                // swizzled slot offset within chunk
            const ulonglong2 pa = Arow[sl];
            const ulonglong2 pb = Brow[sl];
            const unsigned sel = (e & 1) ? 0x7432u : 0x7410u;
#pragma unroll
            for (int r = 0; r < 2; r++) {
                // f = 2^23 + k (exact), then k - 32768 via one FADD
                float wf = __uint_as_float(__byte_perm(w[r][e >> 1], 0x4B000000u, sel))
                           - 8421376.0f;
                unsigned long long w2 = pack_dup(wf);
                ffma2(acc[r][0], w2, pa.x);
                ffma2(acc[r][1], w2, pa.y);
                ffma2(acc[r][2], w2, pb.x);
                ffma2(acc[r][3], w2, pb.y);
            }
        }
    }

    // unpack + reduce over the 8 D-slice lanes (groups of 8 within the warp)
    float res[2][8];
#pragma unroll
    for (int r = 0; r < 2; r++)
#pragma unroll
        for (int i = 0; i < 4; i++)
            unpack2(acc[r][i], res[r][2 * i], res[r][2 * i + 1]);
#pragma unroll
    for (int r = 0; r < 2; r++)
#pragma unroll
        for (int b = 0; b < 8; b++) {
            float a = res[r][b];
            a += __shfl_down_sync(0xFFFFFFFFu, a, 4, 8);
            a += __shfl_down_sync(0xFFFFFFFFu, a, 2, 8);
            a += __shfl_down_sync(0xFFFFFFFFu, a, 1, 8);
            res[r][b] = a;
        }

    const float cl = scales[l] * (1.0f / 32768.0f);
    if (j == 0) {
#pragma unroll
        for (int r = 0; r < 2; r++) {
            const int vl = vl0 + r;
            const int vg = blockIdx.x * 128 + vl;
#pragma unroll
            for (int b = 0; b < 8; b++) {
                float lgv = res[r][b] * cl;
                d_out[TOKS_COUNT + ((size_t)t * BATCH + b) * VOCAB + vg] = lgv;
                s_lg[vl * 9 + b] = lgv;
            }
        }
    }
    __syncthreads();

    // ================= fused gumbel + block argmax =================
    {
        const int v_local = tid & 127;
        const int bg      = tid >> 7;            // 0..3 -> b pair
        const int vg      = blockIdx.x * 128 + v_local;
        uint2 sk; sk.x = skx; sk.y = sky;

        unsigned long long key[2];
#pragma unroll
        for (int i = 0; i < 2; i++) {
            const int b = bg * 2 + i;
            const unsigned ctr = (unsigned)b * (unsigned)VOCAB + (unsigned)vg;
            uint2 rr = threefry2x32(sk, 0u, ctr);
            unsigned bits = rr.x ^ rr.y;
            float u01 = __uint_as_float((bits >> 9) | 0x3f800000u) - 1.0f;
            float u   = fmaxf(u01, 1.17549435e-38f);
            float gum = -logf(-logf(u));
            float val = s_lg[v_local * 9 + b] + gum;
            key[i] = ((unsigned long long)orderf(val) << 32)
                   | (unsigned long long)(0xFFFFFFFFu - (unsigned)vg);
        }
#pragma unroll
        for (int off = 16; off; off >>= 1)
#pragma unroll
            for (int i = 0; i < 2; i++) {
                unsigned long long o = __shfl_down_sync(0xFFFFFFFFu, key[i], off);
                if (o > key[i]) key[i] = o;
            }
        if (lane == 0) {
            s_wbest[warp][0] = key[0];
            s_wbest[warp][1] = key[1];
        }
    }
    __syncthreads();

    // warp 0 merges 16 warps x 2 keys -> 8 per-b bests -> atomicMax
    if (warp == 0) {
        const int w = lane >> 1;                  // source warp
        const int i = lane & 1;
        unsigned long long key = s_wbest[w][i];
        // merge the 4 warps sharing the same (w>>2, i): lanes stride 2, width 8
        {
            unsigned long long o = __shfl_down_sync(0xFFFFFFFFu, key, 4, 8);
            if (o > key) key = o;
            o = __shfl_down_sync(0xFFFFFFFFu, key, 2, 8);
            if (o > key) key = o;
        }
        if ((lane & 7) < 2) {
            const int b = ((lane >> 3) << 1) | (lane & 1);
            atomicMax(&g_bestA[t * BATCH + b], key);
        }
    }
}

// ---------------------------------------------------------------------------
// Kernel 3: final token decode for all steps
// ---------------------------------------------------------------------------
__global__ void finalize_kernel(float* __restrict__ d_out) {
    int i = threadIdx.x;
    if (i < TSTEPS * BATCH) d_out[i] = decode_tok(g_bestA[i]);
}

// ---------------------------------------------------------------------------
// Launch
// ---------------------------------------------------------------------------
extern "C" void kernel_launch(void* const* d_in, const int* in_sizes, int n_in,
                              void* d_out, int out_size) {
    const float* x0     = (const float*)d_in[0];   // [8,1024]
    const int*   seeds  = (const int*)d_in[1];     // [4,65536]
    const float* scales = (const float*)d_in[2];   // [4]
    float* out = (float*)d_out;

    // host-side subkey chain (input-independent, deterministic):
    // key_0 = key(1) = (0,1); each step: new_key = tf(key,0,0), sk = tf(key,0,1)
    unsigned skx[TSTEPS], sky[TSTEPS];
    {
        uint2 key; key.x = 0u; key.y = 1u;
        for (int t = 0; t < TSTEPS; t++) {
            uint2 nk = threefry2x32(key, 0u, 0u);
            uint2 sk = threefry2x32(key, 0u, 1u);
            skx[t] = sk.x; sky[t] = sk.y;
            key = nk;
        }
    }

    decompress_kernel<<<NSEEDS_TOT / 256, 256>>>(seeds);

    for (int t = 0; t < TSTEPS; t++) {
        step_kernel<<<VOCAB / 128, NTHREADS>>>(t, scales, out, skx[t], sky[t], x0);
    }
    finalize_kernel<<<1, 128>>>(out);
}

// round 7
// speedup vs baseline: 3.5801x; 1.1665x over previous
#include <cuda_runtime.h>
#include <cstdint>
#include <cstddef>

// ---------------------------------------------------------------------------
// Problem constants
// ---------------------------------------------------------------------------
#define VOCAB   16384
#define DDIM    1024
#define BATCH   8
#define TSTEPS  16
#define NLAYERS 4
#define LFSR_POLY 0x100Bu           // 69643 & 0xFFFF (bits 0,1,3,12)
#define NSEEDS_TOT (NLAYERS * 65536)   // 262144

// toks [T,B] (as float) followed by logits [T,B,V] in d_out (float32)
#define TOKS_COUNT (TSTEPS*BATCH)

#define NTHREADS 512
#define NWARPS   16

// ---------------------------------------------------------------------------
// Device scratch (static globals: allocation-free)
// ---------------------------------------------------------------------------
// signed-int8 weight planes: klo_s = (k&255)-128, khi_s = (k>>8)-128
__device__ unsigned char g_wlo[(size_t)NLAYERS * VOCAB * DDIM];  // 64 MB
__device__ unsigned char g_whi[(size_t)NLAYERS * VOCAB * DDIM];  // 64 MB
__device__ unsigned long long g_bestA[TSTEPS * BATCH];  // per-step packed (ordered_val<<32)|(~v)

// ---------------------------------------------------------------------------
// threefry2x32-20 (exact JAX implementation), host+device
// ---------------------------------------------------------------------------
__host__ __device__ __forceinline__ unsigned rotl32(unsigned x, int r) {
#ifdef __CUDA_ARCH__
    return __funnelshift_l(x, x, r);
#else
    return (x << r) | (x >> (32 - r));
#endif
}

__host__ __device__ __forceinline__ uint2 threefry2x32(uint2 key, unsigned c0, unsigned c1) {
    unsigned ks0 = key.x, ks1 = key.y;
    unsigned ks2 = ks0 ^ ks1 ^ 0x1BD11BDAu;
    unsigned x0 = c0 + ks0;
    unsigned x1 = c1 + ks1;
#define TF_R4(a,b,c,d)                                              \
    x0 += x1; x1 = rotl32(x1,(a)); x1 ^= x0;                        \
    x0 += x1; x1 = rotl32(x1,(b)); x1 ^= x0;                        \
    x0 += x1; x1 = rotl32(x1,(c)); x1 ^= x0;                        \
    x0 += x1; x1 = rotl32(x1,(d)); x1 ^= x0;
    TF_R4(13,15,26,6);   x0 += ks1; x1 += ks2 + 1u;
    TF_R4(17,29,16,24);  x0 += ks2; x1 += ks0 + 2u;
    TF_R4(13,15,26,6);   x0 += ks0; x1 += ks1 + 3u;
    TF_R4(17,29,16,24);  x0 += ks1; x1 += ks2 + 4u;
    TF_R4(13,15,26,6);   x0 += ks2; x1 += ks0 + 5u;
#undef TF_R4
    uint2 out; out.x = x0; out.y = x1; return out;
}

// ordered-uint encoding of float for monotone unsigned compare
__device__ __forceinline__ unsigned orderf(float f) {
    unsigned u = __float_as_uint(f);
    return (u & 0x80000000u) ? ~u : (u | 0x80000000u);
}

__device__ __forceinline__ float decode_tok(unsigned long long k) {
    return (float)(0xFFFFFFFFu - (unsigned)(k & 0xFFFFFFFFu));
}

// ---------------------------------------------------------------------------
// Kernel 1: LFSR decompression -> two s8 planes, one thread per seed.
// Also zeroes g_bestA (runs first in every graph replay -> deterministic).
// ---------------------------------------------------------------------------
__global__ void decompress_kernel(const int* __restrict__ seeds) {
    int sid = blockIdx.x * blockDim.x + threadIdx.x;   // 0 .. 262143
    if (sid < TSTEPS * BATCH) g_bestA[sid] = 0ull;
    unsigned state = ((unsigned)seeds[sid]) & 0xFFFFu;
    uint4* lo = reinterpret_cast<uint4*>(g_wlo + (size_t)sid * 256);
    uint4* hi = reinterpret_cast<uint4*>(g_whi + (size_t)sid * 256);
#pragma unroll 4
    for (int m = 0; m < 16; m++) {
        unsigned wl[4] = {0u, 0u, 0u, 0u};
        unsigned wh[4] = {0u, 0u, 0u, 0u};
#pragma unroll
        for (int e = 0; e < 16; e++) {
            unsigned bl = (state & 0xFFu) ^ 0x80u;          // klo - 128 as s8
            unsigned bh = ((state >> 8) & 0xFFu) ^ 0x80u;   // khi - 128 as s8
            wl[e >> 2] |= bl << ((e & 3) * 8);
            wh[e >> 2] |= bh << ((e & 3) * 8);
            unsigned fb = __popc(state & LFSR_POLY) & 1u;
            state = ((state >> 1) | (fb << 15)) & 0xFFFFu;
        }
        uint4 ul; ul.x = wl[0]; ul.y = wl[1]; ul.z = wl[2]; ul.w = wl[3];
        uint4 uh; uh.x = wh[0]; uh.y = wh[1]; uh.z = wh[2]; uh.w = wh[3];
        lo[m] = ul;
        hi[m] = uh;
    }
}

// ---------------------------------------------------------------------------
// Kernel 2: fused step kernel. 128 blocks x 512 threads, 128 vocab rows/block.
//   (a) inline prep: layernorm + int8 quantize -> packed q (u32 = 4 d), Sq, 1/as
//   (b) dp4a integer matmul on the two s8 planes
//   (c) fused gumbel-argmax -> atomicMax g_bestA[t]
// q smem layout: per m-block of 32 d4-groups, slot o = 32m + j + 8*e4
// (d4 = 4j + 32m + e4) -> conflict-free LDS.128 across the 8 j-lanes.
// ---------------------------------------------------------------------------
__global__ void __launch_bounds__(NTHREADS) step_kernel(int t, const float* __restrict__ scales,
                                                        float* __restrict__ d_out,
                                                        unsigned skx, unsigned sky,
                                                        const float* __restrict__ x0) {
    __shared__ uint4 s_qA[256];                     // packed q, b0..3, 4 KB
    __shared__ uint4 s_qB[256];                     // packed q, b4..7, 4 KB
    __shared__ float s_lg[128 * 9];                 // logits [v_local][b], padded
    __shared__ float s_red[NWARPS][8];
    __shared__ float s_bc[8];                       // broadcast: mu / rstd / as
    __shared__ float s_sq[8];                       // Sq[b] (exact in float)
    __shared__ float s_inv[8];                      // 1/as[b]
    __shared__ unsigned long long s_wbest[NWARPS][2];

    const int tid  = threadIdx.x;
    const int warp = tid >> 5;
    const int lane = tid & 31;

    // ================= inline prep =================
    // thread handles d0 = 2*tid, d1 = 2*tid+1
    float v[2][8];
#pragma unroll
    for (int k = 0; k < 2; k++) {
        const int d = 2 * tid + k;
        if (d < DDIM - t) {
#pragma unroll
            for (int b = 0; b < 8; b++) v[k][b] = x0[b * DDIM + d + t];
        } else {
            const int s = d + t - DDIM;   // 0..t-1
#pragma unroll
            for (int b = 0; b < 8; b++) v[k][b] = decode_tok(g_bestA[s * BATCH + b]);
        }
    }

    // ---- mean ----
    float part[8];
#pragma unroll
    for (int b = 0; b < 8; b++) part[b] = v[0][b] + v[1][b];
#pragma unroll
    for (int off = 16; off; off >>= 1)
#pragma unroll
        for (int b = 0; b < 8; b++) part[b] += __shfl_down_sync(0xFFFFFFFFu, part[b], off);
    if (lane == 0)
#pragma unroll
        for (int b = 0; b < 8; b++) s_red[warp][b] = part[b];
    __syncthreads();
    if (warp == 0 && lane < 8) {
        const int b = lane;
        float s = 0.0f;
#pragma unroll
        for (int w = 0; w < NWARPS; w++) s += s_red[w][b];
        s_bc[b] = s * (1.0f / DDIM);
    }
    __syncthreads();
    float mu[8];
#pragma unroll
    for (int b = 0; b < 8; b++) mu[b] = s_bc[b];
    __syncthreads();

    // ---- variance ----
#pragma unroll
    for (int b = 0; b < 8; b++) {
        float d0 = v[0][b] - mu[b], d1 = v[1][b] - mu[b];
        part[b] = d0 * d0 + d1 * d1;
    }
#pragma unroll
    for (int off = 16; off; off >>= 1)
#pragma unroll
        for (int b = 0; b < 8; b++) part[b] += __shfl_down_sync(0xFFFFFFFFu, part[b], off);
    if (lane == 0)
#pragma unroll
        for (int b = 0; b < 8; b++) s_red[warp][b] = part[b];
    __syncthreads();
    if (warp == 0 && lane < 8) {
        const int b = lane;
        float s = 0.0f;
#pragma unroll
        for (int w = 0; w < NWARPS; w++) s += s_red[w][b];
        s_bc[b] = 1.0f / sqrtf(s * (1.0f / DDIM) + 1e-5f);
    }
    __syncthreads();
    float xn[2][8];
#pragma unroll
    for (int k = 0; k < 2; k++)
#pragma unroll
        for (int b = 0; b < 8; b++) xn[k][b] = (v[k][b] - mu[b]) * s_bc[b];
    __syncthreads();

    // ---- max |xn| ----
#pragma unroll
    for (int b = 0; b < 8; b++) part[b] = fmaxf(fabsf(xn[0][b]), fabsf(xn[1][b]));
#pragma unroll
    for (int off = 16; off; off >>= 1)
#pragma unroll
        for (int b = 0; b < 8; b++) part[b] = fmaxf(part[b], __shfl_down_sync(0xFFFFFFFFu, part[b], off));
    if (lane == 0)
#pragma unroll
        for (int b = 0; b < 8; b++) s_red[warp][b] = part[b];
    __syncthreads();
    if (warp == 0 && lane < 8) {
        const int b = lane;
        float s = s_red[0][b];
#pragma unroll
        for (int w = 1; w < NWARPS; w++) s = fmaxf(s, s_red[w][b]);
        float as = 127.0f / fmaxf(s, 1e-5f);
        s_bc[b]  = as;
        s_inv[b] = 1.0f / as;
    }
    __syncthreads();

    // ---- int8 quantize ----
    int q[2][8];
#pragma unroll
    for (int k = 0; k < 2; k++)
#pragma unroll
        for (int b = 0; b < 8; b++)
            q[k][b] = (int)rintf(fminf(fmaxf(xn[k][b] * s_bc[b], -127.0f), 127.0f));

    // ---- Sq[b] reduction (exact in fp32) ----
#pragma unroll
    for (int b = 0; b < 8; b++) part[b] = (float)(q[0][b] + q[1][b]);
#pragma unroll
    for (int off = 16; off; off >>= 1)
#pragma unroll
        for (int b = 0; b < 8; b++) part[b] += __shfl_down_sync(0xFFFFFFFFu, part[b], off);
    if (lane == 0)
#pragma unroll
        for (int b = 0; b < 8; b++) s_red[warp][b] = part[b];
    __syncthreads();
    if (warp == 0 && lane < 8) {
        const int b = lane;
        float s = 0.0f;
#pragma unroll
        for (int w = 0; w < NWARPS; w++) s += s_red[w][b];
        s_sq[b] = s;
    }

    // ---- pack q (4 consecutive d per u32) and store swizzled ----
    {
        unsigned half[8], other[8];
#pragma unroll
        for (int b = 0; b < 8; b++)
            half[b] = (unsigned)(q[0][b] & 0xFF) | ((unsigned)(q[1][b] & 0xFF) << 8);
#pragma unroll
        for (int b = 0; b < 8; b++)
            other[b] = __shfl_down_sync(0xFFFFFFFFu, half[b], 1);
        if ((tid & 1) == 0) {
            const int d4 = tid >> 1;              // 0..255
            const int m  = d4 >> 5;
            const int i  = d4 & 31;
            const int jj = i >> 2;
            const int e4 = i & 3;
            const int o  = 32 * m + jj + 8 * e4;
            uint4 qa, qb;
            qa.x = half[0] | (other[0] << 16);
            qa.y = half[1] | (other[1] << 16);
            qa.z = half[2] | (other[2] << 16);
            qa.w = half[3] | (other[3] << 16);
            qb.x = half[4] | (other[4] << 16);
            qb.y = half[5] | (other[5] << 16);
            qb.z = half[6] | (other[6] << 16);
            qb.w = half[7] | (other[7] << 16);
            s_qA[o] = qa;
            s_qB[o] = qb;
        }
    }
    __syncthreads();

    // ================= dp4a matmul =================
    // warp covers 8 rows; lane (g, j): g = lane>>3 -> 2 rows, j = lane&7 -> d-slice
    const int l   = t & 3;
    const int g   = lane >> 3;
    const int j   = lane & 7;
    const int vl0 = warp * 8 + g * 2;
    const int v0  = blockIdx.x * 128 + vl0;

    const uint4* lo0 = reinterpret_cast<const uint4*>(
        g_wlo + ((size_t)l * VOCAB + v0) * DDIM);   // 64 uint4 per row
    const uint4* hi0 = reinterpret_cast<const uint4*>(
        g_whi + ((size_t)l * VOCAB + v0) * DDIM);

    int accL[2][8], accH[2][8];
#pragma unroll
    for (int r = 0; r < 2; r++)
#pragma unroll
        for (int b = 0; b < 8; b++) { accL[r][b] = 0; accH[r][b] = 0; }

#pragma unroll 2
    for (int m = 0; m < 8; m++) {
        const int c = j + 8 * m;                  // uint4 index within row
        uint4 L0 = lo0[c];
        uint4 L1 = lo0[c + 64];
        uint4 H0 = hi0[c];
        uint4 H1 = hi0[c + 64];
        unsigned Lw[2][4] = {{L0.x, L0.y, L0.z, L0.w}, {L1.x, L1.y, L1.z, L1.w}};
        unsigned Hw[2][4] = {{H0.x, H0.y, H0.z, H0.w}, {H1.x, H1.y, H1.z, H1.w}};
#pragma unroll
        for (int e4 = 0; e4 < 4; e4++) {
            const int o = 32 * m + j + 8 * e4;
            const uint4 qa = s_qA[o];
            const uint4 qb = s_qB[o];
            const int qv[8] = {(int)qa.x, (int)qa.y, (int)qa.z, (int)qa.w,
                               (int)qb.x, (int)qb.y, (int)qb.z, (int)qb.w};
#pragma unroll
            for (int r = 0; r < 2; r++) {
                const int wl = (int)Lw[r][e4];
                const int wh = (int)Hw[r][e4];
#pragma unroll
                for (int b = 0; b < 8; b++) {
                    accL[r][b] = __dp4a(qv[b], wl, accL[r][b]);
                    accH[r][b] = __dp4a(qv[b], wh, accH[r][b]);
                }
            }
        }
    }

    // reduce over the 8 D-slice lanes (groups of 8 within the warp)
#pragma unroll
    for (int r = 0; r < 2; r++)
#pragma unroll
        for (int b = 0; b < 8; b++) {
            int aL = accL[r][b], aH = accH[r][b];
            aL += __shfl_down_sync(0xFFFFFFFFu, aL, 4, 8);
            aL += __shfl_down_sync(0xFFFFFFFFu, aL, 2, 8);
            aL += __shfl_down_sync(0xFFFFFFFFu, aL, 1, 8);
            aH += __shfl_down_sync(0xFFFFFFFFu, aH, 4, 8);
            aH += __shfl_down_sync(0xFFFFFFFFu, aH, 2, 8);
            aH += __shfl_down_sync(0xFFFFFFFFu, aH, 1, 8);
            accL[r][b] = aL; accH[r][b] = aH;
        }

    const float cl = scales[l] * (1.0f / 32768.0f);
    if (j == 0) {
#pragma unroll
        for (int r = 0; r < 2; r++) {
            const int vl = vl0 + r;
            const int vg = blockIdx.x * 128 + vl;
#pragma unroll
            for (int b = 0; b < 8; b++) {
                // k-32768 = 256*khi_s + klo_s + 128
                float S = fmaf(256.0f, (float)accH[r][b],
                               fmaf(128.0f, s_sq[b], (float)accL[r][b]));
                float lgv = S * cl * s_inv[b];
                d_out[TOKS_COUNT + ((size_t)t * BATCH + b) * VOCAB + vg] = lgv;
                s_lg[vl * 9 + b] = lgv;
            }
        }
    }
    __syncthreads();

    // ================= fused gumbel + block argmax =================
    {
        const int v_local = tid & 127;
        const int bg      = tid >> 7;            // 0..3 -> b pair
        const int vg      = blockIdx.x * 128 + v_local;
        uint2 sk; sk.x = skx; sk.y = sky;

        unsigned long long key[2];
#pragma unroll
        for (int i = 0; i < 2; i++) {
            const int b = bg * 2 + i;
            const unsigned ctr = (unsigned)b * (unsigned)VOCAB + (unsigned)vg;
            uint2 rr = threefry2x32(sk, 0u, ctr);
            unsigned bits = rr.x ^ rr.y;
            float u01 = __uint_as_float((bits >> 9) | 0x3f800000u) - 1.0f;
            float u   = fmaxf(u01, 1.17549435e-38f);
            float gum = -logf(-logf(u));
            float val = s_lg[v_local * 9 + b] + gum;
            key[i] = ((unsigned long long)orderf(val) << 32)
                   | (unsigned long long)(0xFFFFFFFFu - (unsigned)vg);
        }
#pragma unroll
        for (int off = 16; off; off >>= 1)
#pragma unroll
            for (int i = 0; i < 2; i++) {
                unsigned long long o = __shfl_down_sync(0xFFFFFFFFu, key[i], off);
                if (o > key[i]) key[i] = o;
            }
        if (lane == 0) {
            s_wbest[warp][0] = key[0];
            s_wbest[warp][1] = key[1];
        }
    }
    __syncthreads();

    // warp 0 merges 16 warps x 2 keys -> 8 per-b bests -> atomicMax
    if (warp == 0) {
        const int w = lane >> 1;                  // source warp
        const int i = lane & 1;
        unsigned long long key = s_wbest[w][i];
        {
            unsigned long long o = __shfl_down_sync(0xFFFFFFFFu, key, 4, 8);
            if (o > key) key = o;
            o = __shfl_down_sync(0xFFFFFFFFu, key, 2, 8);
            if (o > key) key = o;
        }
        if ((lane & 7) < 2) {
            const int b = ((lane >> 3) << 1) | (lane & 1);
            atomicMax(&g_bestA[t * BATCH + b], key);
        }
    }
}

// ---------------------------------------------------------------------------
// Kernel 3: final token decode for all steps
// ---------------------------------------------------------------------------
__global__ void finalize_kernel(float* __restrict__ d_out) {
    int i = threadIdx.x;
    if (i < TSTEPS * BATCH) d_out[i] = decode_tok(g_bestA[i]);
}

// ---------------------------------------------------------------------------
// Launch
// ---------------------------------------------------------------------------
extern "C" void kernel_launch(void* const* d_in, const int* in_sizes, int n_in,
                              void* d_out, int out_size) {
    const float* x0     = (const float*)d_in[0];   // [8,1024]
    const int*   seeds  = (const int*)d_in[1];     // [4,65536]
    const float* scales = (const float*)d_in[2];   // [4]
    float* out = (float*)d_out;

    // host-side subkey chain (input-independent, deterministic):
    // key_0 = key(1) = (0,1); each step: new_key = tf(key,0,0), sk = tf(key,0,1)
    unsigned skx[TSTEPS], sky[TSTEPS];
    {
        uint2 key; key.x = 0u; key.y = 1u;
        for (int t = 0; t < TSTEPS; t++) {
            uint2 nk = threefry2x32(key, 0u, 0u);
            uint2 sk = threefry2x32(key, 0u, 1u);
            skx[t] = sk.x; sky[t] = sk.y;
            key = nk;
        }
    }

    decompress_kernel<<<NSEEDS_TOT / 256, 256>>>(seeds);

    for (int t = 0; t < TSTEPS; t++) {
        step_kernel<<<VOCAB / 128, NTHREADS>>>(t, scales, out, skx[t], sky[t], x0);
    }
    finalize_kernel<<<1, 128>>>(out);
}